// round 9
// baseline (speedup 1.0000x reference)
#include <cuda_runtime.h>
#include <cuda_bf16.h>
#include <math.h>

// Problem constants
#define B_   32
#define C_   256
#define H_   64
#define W_   64
#define MIP_ 8
#define OUP_ 256

// Scratch (device globals — no allocation allowed)
__device__ __align__(16) float g_a [B_ * C_ * (H_ + W_)];   // 4 MiB  (a_h | a_w per plane)
__device__ __align__(16) float g_y [B_ * MIP_ * 128];       // y after BN+hswish (128 KB)
__device__ __align__(16) float g_gh[B_ * OUP_ * H_];        // 2 MiB
__device__ __align__(16) float g_gw[B_ * OUP_ * W_];        // 2 MiB

// ---------------------------------------------------------------------------
// K1: per-(b,c) plane stats -> a[plane][0..127].  ONE plane per CTA
// (measured best: regs=32, occ~90%, 28.9us).
//   a_h[h] = (rowsum[h] + softmax_h(rowmax)[h]) / 64
//   a_w[w] = (colsum[w] + softmax_w(colmax)[w]) / 64
// ---------------------------------------------------------------------------
__global__ __launch_bounds__(256) void k1_stats(const float* __restrict__ x)
{
    __shared__ float rmax[64], rsum[64], cmax[64], csum[64];
    __shared__ float pmax[16][68], psum[16][68];   // pitch 68: conflict-free f4 stores

    const int tid = threadIdx.x;
    const long plane = blockIdx.x;                 // 0 .. B*C-1
    const float4* xp = reinterpret_cast<const float4*>(x) + plane * 1024;

    float4 v[4];
    #pragma unroll
    for (int i = 0; i < 4; i++) v[i] = xp[i * 256 + tid];

    // Row reductions: 16 consecutive lanes cover one full row per i
    #pragma unroll
    for (int i = 0; i < 4; i++) {
        float mx = fmaxf(fmaxf(v[i].x, v[i].y), fmaxf(v[i].z, v[i].w));
        float sm = (v[i].x + v[i].y) + (v[i].z + v[i].w);
        #pragma unroll
        for (int o = 1; o < 16; o <<= 1) {
            mx = fmaxf(mx, __shfl_xor_sync(0xFFFFFFFFu, mx, o));
            sm += __shfl_xor_sync(0xFFFFFFFFu, sm, o);
        }
        if ((tid & 15) == 0) {
            int r = i * 16 + (tid >> 4);
            rmax[r] = mx; rsum[r] = sm;
        }
    }

    // Column partials: this thread owns cols 4k..4k+3 (k = tid&15) over 4 rows
    float cm0 = v[0].x, cm1 = v[0].y, cm2 = v[0].z, cm3 = v[0].w;
    float cs0 = v[0].x, cs1 = v[0].y, cs2 = v[0].z, cs3 = v[0].w;
    #pragma unroll
    for (int i = 1; i < 4; i++) {
        cm0 = fmaxf(cm0, v[i].x); cs0 += v[i].x;
        cm1 = fmaxf(cm1, v[i].y); cs1 += v[i].y;
        cm2 = fmaxf(cm2, v[i].z); cs2 += v[i].z;
        cm3 = fmaxf(cm3, v[i].w); cs3 += v[i].w;
    }
    {
        int g = tid >> 4, k = tid & 15;
        *reinterpret_cast<float4*>(&pmax[g][k * 4]) = make_float4(cm0, cm1, cm2, cm3);
        *reinterpret_cast<float4*>(&psum[g][k * 4]) = make_float4(cs0, cs1, cs2, cs3);
    }
    __syncthreads();

    if (tid < 64) {
        float m = pmax[0][tid], s = psum[0][tid];
        #pragma unroll
        for (int g = 1; g < 16; g++) { m = fmaxf(m, pmax[g][tid]); s += psum[g][tid]; }
        cmax[tid] = m; csum[tid] = s;
    }
    __syncthreads();

    // Softmax + emit: warp 0 -> rows (a_h), warp 1 -> cols (a_w)
    const int w    = tid >> 5;
    const int lane = tid & 31;
    if (w < 2) {
        const float* ma = (w == 0) ? rmax : cmax;
        const float* sa = (w == 0) ? rsum : csum;
        float v0 = ma[lane], v1 = ma[lane + 32];
        float m = fmaxf(v0, v1);
        #pragma unroll
        for (int o = 16; o > 0; o >>= 1) m = fmaxf(m, __shfl_xor_sync(0xFFFFFFFFu, m, o));
        float e0 = __expf(v0 - m), e1 = __expf(v1 - m);
        float s = e0 + e1;
        #pragma unroll
        for (int o = 16; o > 0; o >>= 1) s += __shfl_xor_sync(0xFFFFFFFFu, s, o);
        float inv = 1.f / s;
        float* ob = g_a + plane * 128 + w * 64;
        ob[lane]      = (sa[lane]      + e0 * inv) * 0.015625f;   // /64
        ob[lane + 32] = (sa[lane + 32] + e1 * inv) * 0.015625f;
    }
}

// ---------------------------------------------------------------------------
// K2a: per batch b — y = hswish(BN(w1 @ a)) -> g_y[b][m][128]
//   phase1: 8 warps, warp = 32-c slice, lane = s4 (float4 of s), MLP~8
//   phase2: reduce 8 partials + BN + hswish, coalesced f4 store to g_y
// ---------------------------------------------------------------------------
__global__ __launch_bounds__(256) void k2a_y(const float* __restrict__ w1,
                                             const float* __restrict__ gamma,
                                             const float* __restrict__ beta,
                                             const float* __restrict__ mean,
                                             const float* __restrict__ var)
{
    __shared__ float w1s[MIP_ * C_];       // 8 KB
    __shared__ float part[8 * 32 * 33];    // [cgrp][lane(s4)][33]  ~33 KB, pitch 33

    const int tid = threadIdx.x;
    const int b   = blockIdx.x;

    for (int i = tid; i < MIP_ * C_; i += 256) w1s[i] = w1[i];
    __syncthreads();

    // -------- phase 1
    {
        const int wrp  = tid >> 5;         // cgrp 0..7
        const int lane = tid & 31;         // s4 0..31
        const float4* ap = reinterpret_cast<const float4*>(g_a) +
                           ((long)b * C_ + wrp * 32) * 32 + lane;

        float acc[MIP_][4];
        #pragma unroll
        for (int m = 0; m < MIP_; m++)
            #pragma unroll
            for (int j = 0; j < 4; j++) acc[m][j] = 0.f;

        #pragma unroll 4
        for (int k = 0; k < 32; k++) {
            float4 av = ap[k * 32];                     // a[b][c][s4*4..]
            const float* wc = &w1s[wrp * 32 + k];       // w1[m][c], broadcast
            #pragma unroll
            for (int m = 0; m < MIP_; m++) {
                float wv = wc[m * C_];
                acc[m][0] = fmaf(wv, av.x, acc[m][0]);
                acc[m][1] = fmaf(wv, av.y, acc[m][1]);
                acc[m][2] = fmaf(wv, av.z, acc[m][2]);
                acc[m][3] = fmaf(wv, av.w, acc[m][3]);
            }
        }
        float* pb = &part[(wrp * 32 + lane) * 33];
        #pragma unroll
        for (int m = 0; m < MIP_; m++)
            #pragma unroll
            for (int j = 0; j < 4; j++) pb[m * 4 + j] = acc[m][j];
    }
    __syncthreads();

    // -------- phase 2: reduce c-groups, BN + hswish, coalesced store to g_y
    {
        const int m  = tid >> 5;
        const int s4 = tid & 31;
        const float sc = gamma[m] * rsqrtf(var[m] + 1e-5f);
        const float sf = beta[m] - mean[m] * sc;
        float r[4];
        #pragma unroll
        for (int j = 0; j < 4; j++) {
            float s = 0.f;
            #pragma unroll
            for (int g = 0; g < 8; g++) s += part[(g * 32 + s4) * 33 + m * 4 + j];
            float v = fmaf(s, sc, sf);
            r[j] = v * fminf(fmaxf(v + 3.f, 0.f), 6.f) * (1.f / 6.f);   // hswish
        }
        *reinterpret_cast<float4*>(&g_y[(b * MIP_ + m) * 128 + s4 * 4]) =
            make_float4(r[0], r[1], r[2], r[3]);
    }
}

// ---------------------------------------------------------------------------
// K2b: gates. grid = B_*16 blocks x 256 threads.
// Thread -> (b, o, kind in {gh,gw}, 8-wide h segment): 8 outputs each.
// ---------------------------------------------------------------------------
__global__ __launch_bounds__(256) void k2b_gate(const float* __restrict__ wh,
                                                const float* __restrict__ ww)
{
    __shared__ float ys[MIP_ * 128];          // y for this batch (4 KB)

    const int tid = threadIdx.x;
    const int b   = blockIdx.x >> 4;          // 16 blocks per batch

    for (int i = tid; i < MIP_ * 128; i += 256) ys[i] = g_y[b * (MIP_ * 128) + i];
    __syncthreads();

    const int gidx = blockIdx.x * 256 + tid;
    const int bo   = gidx >> 4;               // b*256 + o
    const int o    = bo & 255;
    const int kind = (gidx >> 3) & 1;         // 0 -> gh, 1 -> gw
    const int seg  = gidx & 7;                // h chunk of 8
    const int base = kind * 64 + seg * 8;

    const float* wrow = (kind ? ww : wh) + o * MIP_;
    const float4 w0 = *reinterpret_cast<const float4*>(wrow);
    const float4 w1v = *reinterpret_cast<const float4*>(wrow + 4);
    float wr[MIP_] = {w0.x, w0.y, w0.z, w0.w, w1v.x, w1v.y, w1v.z, w1v.w};

    float acc[8];
    #pragma unroll
    for (int j = 0; j < 8; j++) acc[j] = 0.f;

    #pragma unroll
    for (int m = 0; m < MIP_; m++) {
        float4 y0 = *reinterpret_cast<const float4*>(&ys[m * 128 + base]);
        float4 y1 = *reinterpret_cast<const float4*>(&ys[m * 128 + base + 4]);
        acc[0] = fmaf(wr[m], y0.x, acc[0]);
        acc[1] = fmaf(wr[m], y0.y, acc[1]);
        acc[2] = fmaf(wr[m], y0.z, acc[2]);
        acc[3] = fmaf(wr[m], y0.w, acc[3]);
        acc[4] = fmaf(wr[m], y1.x, acc[4]);
        acc[5] = fmaf(wr[m], y1.y, acc[5]);
        acc[6] = fmaf(wr[m], y1.z, acc[6]);
        acc[7] = fmaf(wr[m], y1.w, acc[7]);
    }

    float r[8];
    #pragma unroll
    for (int j = 0; j < 8; j++) r[j] = __fdividef(1.f, 1.f + __expf(-acc[j]));

    float* outp = (kind ? g_gw : g_gh) + bo * 64 + seg * 8;
    *reinterpret_cast<float4*>(outp)     = make_float4(r[0], r[1], r[2], r[3]);
    *reinterpret_cast<float4*>(outp + 4) = make_float4(r[4], r[5], r[6], r[7]);
}

// ---------------------------------------------------------------------------
// K3: out = x * g_h[bc,h] * g_w[bc,w]. One block == one (b,c) plane.
// 4 front-batched streaming loads per thread; gw hoisted (constant over k).
// Reverse block order reuses the x tail K1 left in L2.
// ---------------------------------------------------------------------------
__global__ __launch_bounds__(256) void k3_apply(const float* __restrict__ x,
                                                float* __restrict__ out)
{
    const int  bc   = gridDim.x - 1 - blockIdx.x;       // plane index
    const int  tid  = threadIdx.x;
    const long base = (long)bc * 1024 + tid;            // float4 index

    const float4* xp = reinterpret_cast<const float4*>(x);
    float4*       op = reinterpret_cast<float4*>(out);

    float4 xv[4];
    #pragma unroll
    for (int k = 0; k < 4; k++) xv[k] = __ldcs(xp + base + k * 256);

    const float4 gwv = *(reinterpret_cast<const float4*>(g_gw) + bc * 16 + (tid & 15));
    const float* ghp = g_gh + bc * 64;

    #pragma unroll
    for (int k = 0; k < 4; k++) {
        float ghv = ghp[k * 16 + (tid >> 4)];
        float4 ov;
        ov.x = xv[k].x * ghv * gwv.x;
        ov.y = xv[k].y * ghv * gwv.y;
        ov.z = xv[k].z * ghv * gwv.z;
        ov.w = xv[k].w * ghv * gwv.w;
        __stcs(op + base + k * 256, ov);
    }
}

// ---------------------------------------------------------------------------
extern "C" void kernel_launch(void* const* d_in, const int* in_sizes, int n_in,
                              void* d_out, int out_size)
{
    const float* x     = (const float*)d_in[0];
    const float* w1    = (const float*)d_in[1];
    const float* gamma = (const float*)d_in[2];
    const float* beta  = (const float*)d_in[3];
    const float* mean  = (const float*)d_in[4];
    const float* var   = (const float*)d_in[5];
    const float* wh    = (const float*)d_in[6];
    const float* ww    = (const float*)d_in[7];
    float* out = (float*)d_out;

    k1_stats<<<B_ * C_,  256>>>(x);
    k2a_y   <<<B_,       256>>>(w1, gamma, beta, mean, var);
    k2b_gate<<<B_ * 16,  256>>>(wh, ww);
    k3_apply<<<B_ * C_,  256>>>(x, out);
}

// round 10
// speedup vs baseline: 1.0752x; 1.0752x over previous
#include <cuda_runtime.h>
#include <cuda_bf16.h>
#include <math.h>

// Problem constants
#define B_   32
#define C_   256
#define H_   64
#define W_   64
#define MIP_ 8
#define OUP_ 256

#define NCTA 1024            // 148 SMs x 7 CTAs = 1036 >= 1024 -> all co-resident
#define PPC  8               // planes per CTA: 8192 / 1024, exact

// Scratch (device globals — no allocation allowed)
__device__ __align__(16) float g_a [B_ * C_ * (H_ + W_)];   // 4 MiB
__device__ __align__(16) float g_y [B_ * MIP_ * 128];       // 128 KB
__device__ __align__(16) float g_gh[B_ * OUP_ * H_];        // 2 MiB
__device__ __align__(16) float g_gw[B_ * OUP_ * W_];        // 2 MiB
__device__ int g_bar[4];                                    // 3 barriers + done (zero-init)

// Shared-memory union across phases
struct K1Smem {
    float pmax[16][68];
    float psum[16][68];
    float rmax[64], rsum[64], cmax[64], csum[64];
};                                            // 9728 B
struct K2aSmem { float part[8 * 132]; };      // 4224 B
struct K2bSmem { float ys[MIP_ * 128]; };     // 4096 B

// Grid-wide barrier: monotonic counter, reset by the last CTA at kernel end.
__device__ __forceinline__ void grid_barrier(int idx)
{
    __threadfence();                 // each thread publishes its writes
    __syncthreads();
    if (threadIdx.x == 0) {
        atomicAdd(&g_bar[idx], 1);
        while (*(volatile int*)&g_bar[idx] < NCTA) __nanosleep(64);
        __threadfence();             // acquire side
    }
    __syncthreads();
}

__global__ __launch_bounds__(256, 7) void k_all(
    const float* __restrict__ x,
    const float* __restrict__ w1,
    const float* __restrict__ gamma,
    const float* __restrict__ beta,
    const float* __restrict__ mean,
    const float* __restrict__ var,
    const float* __restrict__ wh,
    const float* __restrict__ ww,
    float* __restrict__ out)
{
    __shared__ __align__(16) char sraw[sizeof(K1Smem)];
    K1Smem&  s1 = *reinterpret_cast<K1Smem*>(sraw);
    K2aSmem& s2 = *reinterpret_cast<K2aSmem*>(sraw);
    K2bSmem& s3 = *reinterpret_cast<K2bSmem*>(sraw);

    const int cta = blockIdx.x;
    const int tid = threadIdx.x;

    // ================= Phase 1: per-plane stats -> g_a ======================
    //   a_h[h] = (rowsum[h] + softmax_h(rowmax)[h]) / 64
    //   a_w[w] = (colsum[w] + softmax_w(colmax)[w]) / 64
    for (int pi = 0; pi < PPC; pi++) {
        const long plane = cta + pi * NCTA;
        const float4* xp = reinterpret_cast<const float4*>(x) + plane * 1024;

        float4 v[4];
        #pragma unroll
        for (int i = 0; i < 4; i++) v[i] = xp[i * 256 + tid];

        // Row reductions: 16 consecutive lanes cover one full row per i
        #pragma unroll
        for (int i = 0; i < 4; i++) {
            float mx = fmaxf(fmaxf(v[i].x, v[i].y), fmaxf(v[i].z, v[i].w));
            float sm = (v[i].x + v[i].y) + (v[i].z + v[i].w);
            #pragma unroll
            for (int o = 1; o < 16; o <<= 1) {
                mx = fmaxf(mx, __shfl_xor_sync(0xFFFFFFFFu, mx, o));
                sm += __shfl_xor_sync(0xFFFFFFFFu, sm, o);
            }
            if ((tid & 15) == 0) {
                int r = i * 16 + (tid >> 4);
                s1.rmax[r] = mx; s1.rsum[r] = sm;
            }
        }

        // Column partials: thread owns cols 4k..4k+3 (k = tid&15) over 4 rows
        float cm0 = v[0].x, cm1 = v[0].y, cm2 = v[0].z, cm3 = v[0].w;
        float cs0 = v[0].x, cs1 = v[0].y, cs2 = v[0].z, cs3 = v[0].w;
        #pragma unroll
        for (int i = 1; i < 4; i++) {
            cm0 = fmaxf(cm0, v[i].x); cs0 += v[i].x;
            cm1 = fmaxf(cm1, v[i].y); cs1 += v[i].y;
            cm2 = fmaxf(cm2, v[i].z); cs2 += v[i].z;
            cm3 = fmaxf(cm3, v[i].w); cs3 += v[i].w;
        }
        {
            int g = tid >> 4, k = tid & 15;
            *reinterpret_cast<float4*>(&s1.pmax[g][k * 4]) = make_float4(cm0, cm1, cm2, cm3);
            *reinterpret_cast<float4*>(&s1.psum[g][k * 4]) = make_float4(cs0, cs1, cs2, cs3);
        }
        __syncthreads();

        if (tid < 64) {
            float m = s1.pmax[0][tid], s = s1.psum[0][tid];
            #pragma unroll
            for (int g = 1; g < 16; g++) { m = fmaxf(m, s1.pmax[g][tid]); s += s1.psum[g][tid]; }
            s1.cmax[tid] = m; s1.csum[tid] = s;
        }
        __syncthreads();

        // Softmax + emit: warp 0 -> rows (a_h), warp 1 -> cols (a_w)
        const int w    = tid >> 5;
        const int lane = tid & 31;
        if (w < 2) {
            const float* ma = (w == 0) ? s1.rmax : s1.cmax;
            const float* sa = (w == 0) ? s1.rsum : s1.csum;
            float v0 = ma[lane], v1 = ma[lane + 32];
            float m = fmaxf(v0, v1);
            #pragma unroll
            for (int o = 16; o > 0; o >>= 1) m = fmaxf(m, __shfl_xor_sync(0xFFFFFFFFu, m, o));
            float e0 = __expf(v0 - m), e1 = __expf(v1 - m);
            float s = e0 + e1;
            #pragma unroll
            for (int o = 16; o > 0; o >>= 1) s += __shfl_xor_sync(0xFFFFFFFFu, s, o);
            float inv = 1.f / s;
            float* ob = g_a + plane * 128 + w * 64;
            ob[lane]      = (sa[lane]      + e0 * inv) * 0.015625f;   // /64
            ob[lane + 32] = (sa[lane + 32] + e1 * inv) * 0.015625f;
        }
        __syncthreads();   // protect rmax/rsum/cmax/csum reuse next plane
    }

    grid_barrier(0);       // g_a complete

    // ================= Phase 2a: y = hswish(BN(w1 @ a)) -> g_y ==============
    // CTA (cta<256) owns (b = cta>>3, m = cta&7). Warp w covers c in [32w,32w+32),
    // lane l = s4. No big partial buffer.
    if (cta < 256) {
        const int b = cta >> 3;
        const int m = cta & 7;
        const int w = tid >> 5;
        const int l = tid & 31;

        float acc0 = 0.f, acc1 = 0.f, acc2 = 0.f, acc3 = 0.f;
        const float4* ab = reinterpret_cast<const float4*>(g_a) + ((long)b * C_) * 32 + l;
        const float*  wr = w1 + m * C_;
        #pragma unroll 4
        for (int k = 0; k < 32; k++) {
            int c = w * 32 + k;
            float4 av = ab[c * 32];
            float  wv = __ldg(&wr[c]);
            acc0 = fmaf(wv, av.x, acc0);
            acc1 = fmaf(wv, av.y, acc1);
            acc2 = fmaf(wv, av.z, acc2);
            acc3 = fmaf(wv, av.w, acc3);
        }
        float* pb = &s2.part[w * 132 + l * 4];
        pb[0] = acc0; pb[1] = acc1; pb[2] = acc2; pb[3] = acc3;
        __syncthreads();

        if (tid < 128) {
            float s = 0.f;
            #pragma unroll
            for (int g = 0; g < 8; g++) s += s2.part[g * 132 + tid];
            const float sc = gamma[m] * rsqrtf(var[m] + 1e-5f);
            const float sf = beta[m] - mean[m] * sc;
            float v = fmaf(s, sc, sf);
            g_y[(b * MIP_ + m) * 128 + tid] =
                v * fminf(fmaxf(v + 3.f, 0.f), 6.f) * (1.f / 6.f);    // hswish
        }
    }

    grid_barrier(1);       // g_y complete

    // ================= Phase 2b: gates -> g_gh / g_gw =======================
    // CTA (cta<512): b = cta>>4; thread -> (o, kind, 8-wide h segment).
    if (cta < 512) {
        const int b = cta >> 4;
        for (int i = tid; i < MIP_ * 128; i += 256) s3.ys[i] = g_y[b * (MIP_ * 128) + i];
        __syncthreads();

        const int gidx = cta * 256 + tid;
        const int bo   = gidx >> 4;               // b*256 + o
        const int o    = bo & 255;
        const int kind = (gidx >> 3) & 1;         // 0 -> gh, 1 -> gw
        const int seg  = gidx & 7;                // h chunk of 8
        const int base = kind * 64 + seg * 8;

        const float* wrow = (kind ? ww : wh) + o * MIP_;
        const float4 w0  = *reinterpret_cast<const float4*>(wrow);
        const float4 w1v = *reinterpret_cast<const float4*>(wrow + 4);
        float wr[MIP_] = {w0.x, w0.y, w0.z, w0.w, w1v.x, w1v.y, w1v.z, w1v.w};

        float acc[8];
        #pragma unroll
        for (int j = 0; j < 8; j++) acc[j] = 0.f;

        #pragma unroll
        for (int m = 0; m < MIP_; m++) {
            float4 y0 = *reinterpret_cast<const float4*>(&s3.ys[m * 128 + base]);
            float4 y1 = *reinterpret_cast<const float4*>(&s3.ys[m * 128 + base + 4]);
            acc[0] = fmaf(wr[m], y0.x, acc[0]);
            acc[1] = fmaf(wr[m], y0.y, acc[1]);
            acc[2] = fmaf(wr[m], y0.z, acc[2]);
            acc[3] = fmaf(wr[m], y0.w, acc[3]);
            acc[4] = fmaf(wr[m], y1.x, acc[4]);
            acc[5] = fmaf(wr[m], y1.y, acc[5]);
            acc[6] = fmaf(wr[m], y1.z, acc[6]);
            acc[7] = fmaf(wr[m], y1.w, acc[7]);
        }

        float r[8];
        #pragma unroll
        for (int j = 0; j < 8; j++) r[j] = __fdividef(1.f, 1.f + __expf(-acc[j]));

        float* outp = (kind ? g_gw : g_gh) + bo * 64 + seg * 8;
        *reinterpret_cast<float4*>(outp)     = make_float4(r[0], r[1], r[2], r[3]);
        *reinterpret_cast<float4*>(outp + 4) = make_float4(r[4], r[5], r[6], r[7]);
    }

    grid_barrier(2);       // gates complete

    // ================= Phase 3: out = x * gh[h] * gw[w] =====================
    // Same planes as phase 1, walked in REVERSE (freshest L1/L2 lines first).
    for (int pi = PPC - 1; pi >= 0; pi--) {
        const int  bc   = cta + pi * NCTA;
        const long base = (long)bc * 1024 + tid;

        const float4* xp = reinterpret_cast<const float4*>(x);
        float4*       op = reinterpret_cast<float4*>(out);

        float4 xv[4];
        #pragma unroll
        for (int k = 0; k < 4; k++) xv[k] = xp[base + k * 256];

        const float4 gwv = *(reinterpret_cast<const float4*>(g_gw) + bc * 16 + (tid & 15));
        const float* ghp = g_gh + bc * 64;

        #pragma unroll
        for (int k = 0; k < 4; k++) {
            float ghv = ghp[k * 16 + (tid >> 4)];
            float4 ov;
            ov.x = xv[k].x * ghv * gwv.x;
            ov.y = xv[k].y * ghv * gwv.y;
            ov.z = xv[k].z * ghv * gwv.z;
            ov.w = xv[k].w * ghv * gwv.w;
            __stcs(op + base + k * 256, ov);
        }
    }

    // ================= Cleanup: last CTA resets barrier state ===============
    __syncthreads();
    if (tid == 0) {
        int old = atomicAdd(&g_bar[3], 1);
        if (old == NCTA - 1) {
            g_bar[0] = 0; g_bar[1] = 0; g_bar[2] = 0;
            __threadfence();
            g_bar[3] = 0;
        }
    }
}

// ---------------------------------------------------------------------------
extern "C" void kernel_launch(void* const* d_in, const int* in_sizes, int n_in,
                              void* d_out, int out_size)
{
    const float* x     = (const float*)d_in[0];
    const float* w1    = (const float*)d_in[1];
    const float* gamma = (const float*)d_in[2];
    const float* beta  = (const float*)d_in[3];
    const float* mean  = (const float*)d_in[4];
    const float* var   = (const float*)d_in[5];
    const float* wh    = (const float*)d_in[6];
    const float* ww    = (const float*)d_in[7];
    float* out = (float*)d_out;

    k_all<<<NCTA, 256>>>(x, w1, gamma, beta, mean, var, wh, ww, out);
}

// round 11
// speedup vs baseline: 1.3271x; 1.2342x over previous
#include <cuda_runtime.h>
#include <cuda_bf16.h>
#include <math.h>

// Problem constants
#define B_   32
#define C_   256
#define H_   64
#define W_   64
#define MIP_ 8
#define OUP_ 256

// Scratch (device globals — no allocation allowed)
__device__ __align__(16) float g_a [B_ * C_ * (H_ + W_)];   // 4 MiB  (a_h | a_w per plane)
__device__ __align__(16) float g_y [B_ * MIP_ * 128];       // 128 KB (y after BN+hswish)

// ---------------------------------------------------------------------------
// K1: per-(b,c) plane stats -> a[plane][0..127].  ONE plane per CTA
// (measured best: regs=32, occ~90%, ~29us).
//   a_h[h] = (rowsum[h] + softmax_h(rowmax)[h]) / 64
//   a_w[w] = (colsum[w] + softmax_w(colmax)[w]) / 64
// ---------------------------------------------------------------------------
__global__ __launch_bounds__(256) void k1_stats(const float* __restrict__ x)
{
    __shared__ float rmax[64], rsum[64], cmax[64], csum[64];
    __shared__ float pmax[16][68], psum[16][68];   // pitch 68: conflict-free f4 stores

    const int tid = threadIdx.x;
    const long plane = blockIdx.x;                 // 0 .. B*C-1
    const float4* xp = reinterpret_cast<const float4*>(x) + plane * 1024;

    float4 v[4];
    #pragma unroll
    for (int i = 0; i < 4; i++) v[i] = xp[i * 256 + tid];

    // Row reductions: 16 consecutive lanes cover one full row per i
    #pragma unroll
    for (int i = 0; i < 4; i++) {
        float mx = fmaxf(fmaxf(v[i].x, v[i].y), fmaxf(v[i].z, v[i].w));
        float sm = (v[i].x + v[i].y) + (v[i].z + v[i].w);
        #pragma unroll
        for (int o = 1; o < 16; o <<= 1) {
            mx = fmaxf(mx, __shfl_xor_sync(0xFFFFFFFFu, mx, o));
            sm += __shfl_xor_sync(0xFFFFFFFFu, sm, o);
        }
        if ((tid & 15) == 0) {
            int r = i * 16 + (tid >> 4);
            rmax[r] = mx; rsum[r] = sm;
        }
    }

    // Column partials: this thread owns cols 4k..4k+3 (k = tid&15) over 4 rows
    float cm0 = v[0].x, cm1 = v[0].y, cm2 = v[0].z, cm3 = v[0].w;
    float cs0 = v[0].x, cs1 = v[0].y, cs2 = v[0].z, cs3 = v[0].w;
    #pragma unroll
    for (int i = 1; i < 4; i++) {
        cm0 = fmaxf(cm0, v[i].x); cs0 += v[i].x;
        cm1 = fmaxf(cm1, v[i].y); cs1 += v[i].y;
        cm2 = fmaxf(cm2, v[i].z); cs2 += v[i].z;
        cm3 = fmaxf(cm3, v[i].w); cs3 += v[i].w;
    }
    {
        int g = tid >> 4, k = tid & 15;
        *reinterpret_cast<float4*>(&pmax[g][k * 4]) = make_float4(cm0, cm1, cm2, cm3);
        *reinterpret_cast<float4*>(&psum[g][k * 4]) = make_float4(cs0, cs1, cs2, cs3);
    }
    __syncthreads();

    if (tid < 64) {
        float m = pmax[0][tid], s = psum[0][tid];
        #pragma unroll
        for (int g = 1; g < 16; g++) { m = fmaxf(m, pmax[g][tid]); s += psum[g][tid]; }
        cmax[tid] = m; csum[tid] = s;
    }
    __syncthreads();

    // Softmax + emit: warp 0 -> rows (a_h), warp 1 -> cols (a_w)
    const int w    = tid >> 5;
    const int lane = tid & 31;
    if (w < 2) {
        const float* ma = (w == 0) ? rmax : cmax;
        const float* sa = (w == 0) ? rsum : csum;
        float v0 = ma[lane], v1 = ma[lane + 32];
        float m = fmaxf(v0, v1);
        #pragma unroll
        for (int o = 16; o > 0; o >>= 1) m = fmaxf(m, __shfl_xor_sync(0xFFFFFFFFu, m, o));
        float e0 = __expf(v0 - m), e1 = __expf(v1 - m);
        float s = e0 + e1;
        #pragma unroll
        for (int o = 16; o > 0; o >>= 1) s += __shfl_xor_sync(0xFFFFFFFFu, s, o);
        float inv = 1.f / s;
        float* ob = g_a + plane * 128 + w * 64;
        ob[lane]      = (sa[lane]      + e0 * inv) * 0.015625f;   // /64
        ob[lane + 32] = (sa[lane + 32] + e1 * inv) * 0.015625f;
    }
}

// ---------------------------------------------------------------------------
// K2a: per batch b — y = hswish(BN(w1 @ a)) -> g_y[b][m][128]
//   phase1: 8 warps, warp = 32-c slice, lane = s4 (float4 of s), MLP~8
//   phase2: reduce 8 partials + BN + hswish, coalesced f4 store to g_y
// ---------------------------------------------------------------------------
__global__ __launch_bounds__(256) void k2a_y(const float* __restrict__ w1,
                                             const float* __restrict__ gamma,
                                             const float* __restrict__ beta,
                                             const float* __restrict__ mean,
                                             const float* __restrict__ var)
{
    __shared__ float w1s[MIP_ * C_];       // 8 KB
    __shared__ float part[8 * 32 * 33];    // [cgrp][lane(s4)][33]  ~33 KB, pitch 33

    const int tid = threadIdx.x;
    const int b   = blockIdx.x;

    for (int i = tid; i < MIP_ * C_; i += 256) w1s[i] = w1[i];
    __syncthreads();

    // -------- phase 1
    {
        const int wrp  = tid >> 5;         // cgrp 0..7
        const int lane = tid & 31;         // s4 0..31
        const float4* ap = reinterpret_cast<const float4*>(g_a) +
                           ((long)b * C_ + wrp * 32) * 32 + lane;

        float acc[MIP_][4];
        #pragma unroll
        for (int m = 0; m < MIP_; m++)
            #pragma unroll
            for (int j = 0; j < 4; j++) acc[m][j] = 0.f;

        #pragma unroll 4
        for (int k = 0; k < 32; k++) {
            float4 av = ap[k * 32];                     // a[b][c][s4*4..]
            const float* wc = &w1s[wrp * 32 + k];       // w1[m][c], broadcast
            #pragma unroll
            for (int m = 0; m < MIP_; m++) {
                float wv = wc[m * C_];
                acc[m][0] = fmaf(wv, av.x, acc[m][0]);
                acc[m][1] = fmaf(wv, av.y, acc[m][1]);
                acc[m][2] = fmaf(wv, av.z, acc[m][2]);
                acc[m][3] = fmaf(wv, av.w, acc[m][3]);
            }
        }
        float* pb = &part[(wrp * 32 + lane) * 33];
        #pragma unroll
        for (int m = 0; m < MIP_; m++)
            #pragma unroll
            for (int j = 0; j < 4; j++) pb[m * 4 + j] = acc[m][j];
    }
    __syncthreads();

    // -------- phase 2: reduce c-groups, BN + hswish, coalesced store to g_y
    {
        const int m  = tid >> 5;
        const int s4 = tid & 31;
        const float sc = gamma[m] * rsqrtf(var[m] + 1e-5f);
        const float sf = beta[m] - mean[m] * sc;
        float r[4];
        #pragma unroll
        for (int j = 0; j < 4; j++) {
            float s = 0.f;
            #pragma unroll
            for (int g = 0; g < 8; g++) s += part[(g * 32 + s4) * 33 + m * 4 + j];
            float v = fmaf(s, sc, sf);
            r[j] = v * fminf(fmaxf(v + 3.f, 0.f), 6.f) * (1.f / 6.f);   // hswish
        }
        *reinterpret_cast<float4*>(&g_y[(b * MIP_ + m) * 128 + s4 * 4]) =
            make_float4(r[0], r[1], r[2], r[3]);
    }
}

// ---------------------------------------------------------------------------
// K3f: fused gates + apply. One block == one (b,c) plane.
// Prologue: 4 front-batched __ldcs x loads; load y[b] (4KB, L2-hot);
// 128 threads compute this channel's gates:
//   gh[h] = sigmoid(sum_m wh[c,m] * y[b,m,h])
//   gw[w] = sigmoid(sum_m ww[c,m] * y[b,m,64+w])
// Then stream out = x * gh[h] * gw[w] with __stcs.
// Reverse block order reuses the x tail K1 left in L2.
// ---------------------------------------------------------------------------
__global__ __launch_bounds__(256) void k3_fused(const float* __restrict__ x,
                                                const float* __restrict__ wh,
                                                const float* __restrict__ ww,
                                                float* __restrict__ out)
{
    __shared__ float ysm[MIP_ * 128];      // y for this batch (4 KB)
    __shared__ float gh[64], gw[64];

    const int  bc   = gridDim.x - 1 - blockIdx.x;       // plane index
    const int  b    = bc >> 8;
    const int  c    = bc & 255;
    const int  tid  = threadIdx.x;
    const long base = (long)bc * 1024 + tid;            // float4 index

    const float4* xp = reinterpret_cast<const float4*>(x);
    float4*       op = reinterpret_cast<float4*>(out);

    // Front-batched streaming loads of this plane of x
    float4 xv[4];
    #pragma unroll
    for (int k = 0; k < 4; k++) xv[k] = __ldcs(xp + base + k * 256);

    // Load y[b] cooperatively (1024 floats / 256 threads = one float4 each)
    {
        const float4* yp = reinterpret_cast<const float4*>(g_y + b * (MIP_ * 128));
        *reinterpret_cast<float4*>(&ysm[tid * 4]) = yp[tid];
    }
    __syncthreads();

    // Threads 0..127 compute gates for this channel c
    if (tid < 128) {
        const int kind = tid >> 6;         // 0 -> gh, 1 -> gw
        const int idx  = tid & 63;
        const float* wrow = (kind ? ww : wh) + c * MIP_;
        const float4 w0 = *reinterpret_cast<const float4*>(wrow);
        const float4 w1 = *reinterpret_cast<const float4*>(wrow + 4);
        const float* yb = &ysm[kind * 64 + idx];
        float acc = w0.x * yb[0]
                  + w0.y * yb[128]
                  + w0.z * yb[256]
                  + w0.w * yb[384]
                  + w1.x * yb[512]
                  + w1.y * yb[640]
                  + w1.z * yb[768]
                  + w1.w * yb[896];
        float g = __fdividef(1.f, 1.f + __expf(-acc));
        if (kind) gw[idx] = g; else gh[idx] = g;
    }
    __syncthreads();

    const float4 gwv = *reinterpret_cast<const float4*>(&gw[(tid & 15) * 4]);

    #pragma unroll
    for (int k = 0; k < 4; k++) {
        float ghv = gh[k * 16 + (tid >> 4)];
        float4 ov;
        ov.x = xv[k].x * ghv * gwv.x;
        ov.y = xv[k].y * ghv * gwv.y;
        ov.z = xv[k].z * ghv * gwv.z;
        ov.w = xv[k].w * ghv * gwv.w;
        __stcs(op + base + k * 256, ov);
    }
}

// ---------------------------------------------------------------------------
extern "C" void kernel_launch(void* const* d_in, const int* in_sizes, int n_in,
                              void* d_out, int out_size)
{
    const float* x     = (const float*)d_in[0];
    const float* w1    = (const float*)d_in[1];
    const float* gamma = (const float*)d_in[2];
    const float* beta  = (const float*)d_in[3];
    const float* mean  = (const float*)d_in[4];
    const float* var   = (const float*)d_in[5];
    const float* wh    = (const float*)d_in[6];
    const float* ww    = (const float*)d_in[7];
    float* out = (float*)d_out;

    k1_stats<<<B_ * C_, 256>>>(x);
    k2a_y   <<<B_,      256>>>(w1, gamma, beta, mean, var);
    k3_fused<<<B_ * C_, 256>>>(x, wh, ww, out);
}